// round 3
// baseline (speedup 1.0000x reference)
#include <cuda_runtime.h>

#define NFLAT 4096
#define CH    32
#define CIN   64
#define BATCH 4

// Scratch (allocation-free rule: __device__ globals)
__device__ float gQ[BATCH * CH * NFLAT];   // natural [b][o][hw]; flat == q[b][n][c]
__device__ float gK[BATCH * CH * NFLAT];   // [b][c][m]
__device__ float gV[BATCH * CH * NFLAT];   // flat == v[b][m][c]
__device__ float gY[BATCH * NFLAT * CH];   // [b][n][c]; flat == y2[b][ci][hw]

// ---------------------------------------------------------------------------
// Kernel 1: three 1x1 convs (q, k, v) in natural [b][o][hw] layout
// ---------------------------------------------------------------------------
__global__ __launch_bounds__(256) void qkv_kernel(
    const float* __restrict__ x,
    const float* __restrict__ w1, const float* __restrict__ b1,
    const float* __restrict__ w2, const float* __restrict__ b2,
    const float* __restrict__ w3, const float* __restrict__ b3)
{
    __shared__ float ws[CH * CIN];
    __shared__ float bs[CH];
    int conv = blockIdx.y;
    const float* w    = (conv == 0) ? w1 : (conv == 1) ? w2 : w3;
    const float* bias = (conv == 0) ? b1 : (conv == 1) ? b2 : b3;
    float* o          = (conv == 0) ? gQ : (conv == 1) ? gK : gV;

    int t = threadIdx.x;
    for (int i = t; i < CH * CIN; i += 256) ws[i] = w[i];
    if (t < CH) bs[t] = bias[t];
    __syncthreads();

    int idx = blockIdx.x * 256 + t;      // 0..16383 over (b, hw)
    int b = idx >> 12, hw = idx & 4095;
    const float* xp = x + b * (CIN * NFLAT) + hw;

    float acc[CH];
#pragma unroll
    for (int oc = 0; oc < CH; oc++) acc[oc] = bs[oc];

#pragma unroll 4
    for (int c = 0; c < CIN; c++) {
        float xv = xp[c * NFLAT];
#pragma unroll
        for (int oc = 0; oc < CH; oc++) acc[oc] += ws[oc * CIN + c] * xv;
    }

    float* op = o + b * (CH * NFLAT) + hw;
#pragma unroll
    for (int oc = 0; oc < CH; oc++) op[oc * NFLAT] = acc[oc];
}

// ---------------------------------------------------------------------------
// Kernel 2: fused QK -> batch-softmax -> PV  (flash-style, no attn in HBM).
// CTA handles 32 rows n for ALL 4 batches (softmax couples batches).
// Shared rows padded to 36 floats: float4-aligned and conflict-free at the
// 8-lane smem phase granularity for every access pattern below.
// ---------------------------------------------------------------------------
#define PAD  36
#define BSTR (32 * PAD)               // floats per batch slab = 1152
#define SM_FLOATS (16 * BSTR)         // q,k,v,p = 4 slabs each of 4 batches
#define SM_BYTES  (SM_FLOATS * 4)     // 73728 B

__global__ __launch_bounds__(256) void attn_kernel()
{
    extern __shared__ float sm[];
    float* q_s = sm;                  // [b][i][c]
    float* k_s = sm + 4 * BSTR;       // [b][c][j]
    float* v_s = sm + 8 * BSTR;       // [b][j][c]
    float* p_s = sm + 12 * BSTR;      // [b][i][j]

    int t  = threadIdx.x;
    int n0 = blockIdx.x * 32;

    // Load q tile: 4 b x 32 rows x 32 c (rows contiguous in gmem)
    {
        int r = t >> 1, b = r >> 5, i = r & 31, h = (t & 1) * 16;
        const float* src = gQ + b * (CH * NFLAT) + (n0 + i) * CH + h;
        float* dst = q_s + b * BSTR + i * PAD + h;
#pragma unroll
        for (int u = 0; u < 4; u++)
            *(float4*)(dst + 4 * u) = *(const float4*)(src + 4 * u);
    }

    // GEMM-phase mapping: thread -> (batch bb, 4x4 tile at (i0, j0))
    int bb = t >> 6;
    int tl = t & 63;
    int i0 = (tl >> 3) * 4;
    int j0 = (tl & 7) * 4;
    // Softmax-phase mapping: thread -> (row si, 4 cols at sj), all batches
    int si = t >> 3;
    int sj = (t & 7) * 4;

    float acc[4][4];
#pragma unroll
    for (int a = 0; a < 4; a++)
#pragma unroll
        for (int c = 0; c < 4; c++) acc[a][c] = 0.0f;

    for (int m0 = 0; m0 < NFLAT; m0 += 32) {
        // Load k chunk [b][c][m0..m0+31] and v chunk [b][m0..m0+31][c]
        {
            int r = t >> 1, b = r >> 5, cj = r & 31, h = (t & 1) * 16;
            const float* ksrc = gK + b * (CH * NFLAT) + cj * NFLAT + m0 + h;
            float*       kdst = k_s + b * BSTR + cj * PAD + h;
            const float* vsrc = gV + b * (CH * NFLAT) + (m0 + cj) * CH + h;
            float*       vdst = v_s + b * BSTR + cj * PAD + h;
#pragma unroll
            for (int u = 0; u < 4; u++) {
                *(float4*)(kdst + 4 * u) = *(const float4*)(ksrc + 4 * u);
                *(float4*)(vdst + 4 * u) = *(const float4*)(vsrc + 4 * u);
            }
        }
        __syncthreads();

        // ---- QK: s[ii][jj] = sum_c q[bb][i][c] * k[bb][c][j] ----
        __align__(16) float s[4][4];
#pragma unroll
        for (int a = 0; a < 4; a++)
#pragma unroll
            for (int z = 0; z < 4; z++) s[a][z] = 0.0f;

#pragma unroll
        for (int c = 0; c < 32; c += 4) {
            __align__(16) float qv[4][4], kv[4][4];
#pragma unroll
            for (int ii = 0; ii < 4; ii++)
                *(float4*)qv[ii] = *(const float4*)(q_s + bb * BSTR + (i0 + ii) * PAD + c);
#pragma unroll
            for (int cc = 0; cc < 4; cc++)
                *(float4*)kv[cc] = *(const float4*)(k_s + bb * BSTR + (c + cc) * PAD + j0);
#pragma unroll
            for (int ii = 0; ii < 4; ii++)
#pragma unroll
                for (int cc = 0; cc < 4; cc++)
#pragma unroll
                    for (int jj = 0; jj < 4; jj++)
                        s[ii][jj] += qv[ii][cc] * kv[cc][jj];
        }
#pragma unroll
        for (int ii = 0; ii < 4; ii++)
            *(float4*)(p_s + bb * BSTR + (i0 + ii) * PAD + j0) = *(float4*)s[ii];
        __syncthreads();

        // ---- softmax across the 4 batches (pointwise in (n,m)) ----
        {
            __align__(16) float e[4][4];
#pragma unroll
            for (int b = 0; b < 4; b++)
                *(float4*)e[b] = *(const float4*)(p_s + b * BSTR + si * PAD + sj);
#pragma unroll
            for (int jj = 0; jj < 4; jj++) {
                float mx = fmaxf(fmaxf(e[0][jj], e[1][jj]), fmaxf(e[2][jj], e[3][jj]));
                float e0 = __expf(e[0][jj] - mx);
                float e1 = __expf(e[1][jj] - mx);
                float e2 = __expf(e[2][jj] - mx);
                float e3 = __expf(e[3][jj] - mx);
                float inv = 1.0f / (e0 + e1 + e2 + e3);
                e[0][jj] = e0 * inv; e[1][jj] = e1 * inv;
                e[2][jj] = e2 * inv; e[3][jj] = e3 * inv;
            }
#pragma unroll
            for (int b = 0; b < 4; b++)
                *(float4*)(p_s + b * BSTR + si * PAD + sj) = *(float4*)e[b];
        }
        __syncthreads();

        // ---- PV: acc[ii][cc] += sum_j p[bb][i][j] * v[bb][j][c] ----
#pragma unroll
        for (int j = 0; j < 32; j += 4) {
            __align__(16) float pv[4][4], vvv[4][4];
#pragma unroll
            for (int ii = 0; ii < 4; ii++)
                *(float4*)pv[ii] = *(const float4*)(p_s + bb * BSTR + (i0 + ii) * PAD + j);
#pragma unroll
            for (int jj = 0; jj < 4; jj++)
                *(float4*)vvv[jj] = *(const float4*)(v_s + bb * BSTR + (j + jj) * PAD + j0);
#pragma unroll
            for (int ii = 0; ii < 4; ii++)
#pragma unroll
                for (int jj = 0; jj < 4; jj++)
#pragma unroll
                    for (int cc = 0; cc < 4; cc++)
                        acc[ii][cc] += pv[ii][jj] * vvv[jj][cc];
        }
        __syncthreads();
    }

    // Write y[bb][n][c] (contiguous rows)
    __align__(16) float outv[4];
#pragma unroll
    for (int ii = 0; ii < 4; ii++) {
        outv[0] = acc[ii][0]; outv[1] = acc[ii][1];
        outv[2] = acc[ii][2]; outv[3] = acc[ii][3];
        *(float4*)(gY + bb * (NFLAT * CH) + (n0 + i0 + ii) * CH + j0) = *(float4*)outv;
    }
}

// ---------------------------------------------------------------------------
// Kernel 3: final 1x1 conv. gY flat == y2[b][ci][hw], so rows are contiguous.
// ---------------------------------------------------------------------------
__global__ __launch_bounds__(256) void outconv_kernel(
    const float* __restrict__ w4, const float* __restrict__ b4,
    float* __restrict__ out)
{
    __shared__ float ws[CIN * CH];
    __shared__ float bs[CIN];
    int t = threadIdx.x;
    for (int i = t; i < CIN * CH; i += 256) ws[i] = w4[i];
    if (t < CIN) bs[t] = b4[t];
    __syncthreads();

    int idx = blockIdx.x * 256 + t;
    int b = idx >> 12, hw = idx & 4095;
    const float* yp = gY + b * (CH * NFLAT) + hw;   // y2[b][ci][hw]

    float acc[CIN];
#pragma unroll
    for (int co = 0; co < CIN; co++) acc[co] = bs[co];

#pragma unroll 4
    for (int ci = 0; ci < CH; ci++) {
        float yv = yp[ci * NFLAT];
#pragma unroll
        for (int co = 0; co < CIN; co++) acc[co] += ws[co * CH + ci] * yv;
    }

    float* op = out + b * (CIN * NFLAT) + hw;
#pragma unroll
    for (int co = 0; co < CIN; co++) op[co * NFLAT] = acc[co];
}

// ---------------------------------------------------------------------------
extern "C" void kernel_launch(void* const* d_in, const int* in_sizes, int n_in,
                              void* d_out, int out_size)
{
    const float* x  = (const float*)d_in[0];
    const float* w1 = (const float*)d_in[1];
    const float* b1 = (const float*)d_in[2];
    const float* w2 = (const float*)d_in[3];
    const float* b2 = (const float*)d_in[4];
    const float* w3 = (const float*)d_in[5];
    const float* b3 = (const float*)d_in[6];
    const float* w4 = (const float*)d_in[7];
    const float* b4 = (const float*)d_in[8];
    float* out = (float*)d_out;

    cudaFuncSetAttribute(attn_kernel,
                         cudaFuncAttributeMaxDynamicSharedMemorySize, SM_BYTES);

    qkv_kernel<<<dim3(64, 3), 256>>>(x, w1, b1, w2, b2, w3, b3);
    attn_kernel<<<128, 256, SM_BYTES>>>();
    outconv_kernel<<<64, 256>>>(w4, b4, out);
}